// round 8
// baseline (speedup 1.0000x reference)
#include <cuda_runtime.h>
#include <cuda_bf16.h>
#include <math.h>
#include <stdint.h>

#define BSZ 64
#define NN  256
#define CC  512
#define NC  (NN*CC)     // 131072
#define NNN (NN*NN)     // 65536

// Scratch (no cudaMalloc allowed)
__device__ float g_b1[BSZ*NC];
__device__ float g_b2[BSZ*NC];
__device__ float g_b3[BSZ*NC];
__device__ float g_b4[BSZ*NC];
__device__ float g_S [BSZ*NNN];

// SMEM stage layout: Ah @0 (8KB) | Al @8K | Bh @16K | Bl @24K ; two stages.
#define STG        32768
#define SMEM_TOTAL (2*STG)

__device__ __forceinline__ uint32_t smem_u32(const void* p) {
    uint32_t a;
    asm("{ .reg .u64 t; cvta.to.shared.u64 t, %1; cvt.u32.u64 %0, t; }" : "=r"(a) : "l"(p));
    return a;
}

// [row][k] layout, 128 rows x 64B; swizzle keeps ldmatrix phases conflict-free
__device__ __forceinline__ uint32_t off_rk(uint32_t r, uint32_t cb) {
    return r * 64u + ((((cb >> 4) ^ ((r >> 1) & 3u)) & 3u) << 4) + (cb & 15u);
}
// [k][col] layout, 32 rows x 256B
__device__ __forceinline__ uint32_t off_kn(uint32_t k, uint32_t cb) {
    uint32_t ch = (cb >> 4) ^ (k & 7u);
    return k * 256u + (ch << 4) + (cb & 15u);
}

__device__ __forceinline__ void ldsm4(uint32_t& r0, uint32_t& r1, uint32_t& r2, uint32_t& r3, uint32_t a) {
    asm volatile("ldmatrix.sync.aligned.m8n8.x4.shared.b16 {%0,%1,%2,%3}, [%4];"
                 : "=r"(r0), "=r"(r1), "=r"(r2), "=r"(r3) : "r"(a));
}
__device__ __forceinline__ void ldsm4t(uint32_t& r0, uint32_t& r1, uint32_t& r2, uint32_t& r3, uint32_t a) {
    asm volatile("ldmatrix.sync.aligned.m8n8.x4.trans.shared.b16 {%0,%1,%2,%3}, [%4];"
                 : "=r"(r0), "=r"(r1), "=r"(r2), "=r"(r3) : "r"(a));
}
__device__ __forceinline__ void mma16816(float* c, const uint32_t* a, const uint32_t* b) {
    asm volatile(
        "mma.sync.aligned.m16n8k16.row.col.f32.bf16.bf16.f32 "
        "{%0,%1,%2,%3}, {%4,%5,%6,%7}, {%8,%9}, {%0,%1,%2,%3};"
        : "+f"(c[0]), "+f"(c[1]), "+f"(c[2]), "+f"(c[3])
        : "r"(a[0]), "r"(a[1]), "r"(a[2]), "r"(a[3]), "r"(b[0]), "r"(b[1]));
}

// Convert 8 fp32 -> 8 bf16 hi + 8 bf16 lo, write 16B each.
__device__ __forceinline__ void cvt_store8(const float4 v0, const float4 v1,
                                           char* ph, char* pl) {
    float v[8] = {v0.x, v0.y, v0.z, v0.w, v1.x, v1.y, v1.z, v1.w};
    unsigned short hs[8], ls[8];
    #pragma unroll
    for (int e = 0; e < 8; e++) {
        __nv_bfloat16 hb = __float2bfloat16_rn(v[e]);
        float lf = v[e] - __bfloat162float(hb);
        __nv_bfloat16 lb = __float2bfloat16_rn(lf);
        hs[e] = *(unsigned short*)&hb;
        ls[e] = *(unsigned short*)&lb;
    }
    *(uint4*)ph = *(uint4*)hs;
    *(uint4*)pl = *(uint4*)ls;
}

// ---- split staging: prefetch LDG into regs, commit cvt+STS later ----
// T=0: source row-major rows=tile rows; layout [r][k]. T=1: rows=k; layout [k][c].
template<int T>
__device__ __forceinline__ void stage_load(const float* __restrict__ src, int ld,
                                           int k0, int r0, float4* v, int tid) {
    #pragma unroll
    for (int it = 0; it < 2; it++) {
        int idx = it * 256 + tid;
        const float* p;
        if (T == 0) {
            int r = idx >> 2, cb8 = (idx & 3) * 8;
            p = src + (long)(r0 + r) * ld + k0 + cb8;
        } else {
            int kr = idx >> 4, cb8 = (idx & 15) * 8;
            p = src + (long)(k0 + kr) * ld + r0 + cb8;
        }
        v[2*it]     = *(const float4*)p;
        v[2*it + 1] = *(const float4*)(p + 4);
    }
}
template<int T>
__device__ __forceinline__ void stage_store(const float4* v, char* sh, char* sl, int tid) {
    #pragma unroll
    for (int it = 0; it < 2; it++) {
        int idx = it * 256 + tid;
        uint32_t off;
        if (T == 0) {
            int r = idx >> 2, cb8 = (idx & 3) * 8;
            off = off_rk((uint32_t)r, (uint32_t)cb8 * 2);
        } else {
            int kr = idx >> 4, cb8 = (idx & 15) * 8;
            off = off_kn((uint32_t)kr, (uint32_t)cb8 * 2);
        }
        cvt_store8(v[2*it], v[2*it + 1], sh + off, sl + off);
    }
}
template<int T>
__device__ __forceinline__ void stage_tile(const float* __restrict__ src, int ld,
                                           int k0, int r0,
                                           char* sh, char* sl, int tid) {
    float4 v[4];
    stage_load<T>(src, ld, k0, r0, v, tid);
    stage_store<T>(v, sh, sl, tid);
}

// ---------------------------------------------------------------------------
// bf16x2-split (3-product) tensor-core GEMM.  C[b](M x N) = op(A[b]) @ op(B[b])
//   TA=0: A row-major (M,K).  TA=1: A[m][k] = src[k*lda+m] (adj^T).
//   TB=0: B source (N,K) row-major.  TB=1: B[n][k] = src[k*ldb+n].
//   EPI: 0 store | 1 relu | 2 relu + C_old | 3 relu + Add
// CTA 128x128, BK=32, 256 thr; warp tile 32x64. Double-buffered with
// register-prefetch: LDG(ch+1) issued before MMA(ch), cvt+STS after.
// ---------------------------------------------------------------------------
template<int TA, int TB, int EPI>
__global__ __launch_bounds__(256, 2)
void tc_gemm(const float* __restrict__ A, long sA, int lda,
             const float* __restrict__ B, long sB, int ldb,
             float* __restrict__ C, long sC, int ldc,
             const float* __restrict__ Add, long sAdd, int K)
{
    extern __shared__ char smem[];
    const int tid = threadIdx.x, lane = tid & 31, wid = tid >> 5;
    const int b  = blockIdx.z;
    const int m0 = blockIdx.y * 128;
    const int n0 = blockIdx.x * 128;
    const float* Ab = A + (long)b * sA;
    const float* Bb = B + (long)b * sB;
    float*       Cb = C + (long)b * sC;

    const int am = (wid & 3) * 32;   // warp rows
    const int bn = (wid >> 2) * 64;  // warp cols

    float acc[2][8][4];
    #pragma unroll
    for (int i = 0; i < 2; i++)
        #pragma unroll
        for (int j = 0; j < 8; j++)
            #pragma unroll
            for (int e = 0; e < 4; e++) acc[i][j][e] = 0.f;

    const int nch = K >> 5;

    stage_tile<TA>(Ab, lda, 0, m0, smem,          smem + 8192,  tid);
    stage_tile<TB>(Bb, ldb, 0, n0, smem + 16384,  smem + 24576, tid);
    __syncthreads();

    for (int ch = 0; ch < nch; ch++) {
        const int d = ch & 1;
        char* cur = smem + d * STG;

        // ---- 1) prefetch next chunk's gmem data into registers (no stalls) ----
        float4 pa[4], pb[4];
        const bool more = (ch + 1 < nch);
        if (more) {
            stage_load<TA>(Ab, lda, (ch + 1) << 5, m0, pa, tid);
            stage_load<TB>(Bb, ldb, (ch + 1) << 5, n0, pb, tid);
        }

        const uint32_t uAh = smem_u32(cur);
        const uint32_t uAl = uAh + 8192;
        const uint32_t uBh = uAh + 16384;
        const uint32_t uBl = uAh + 24576;

        // ---- 2) MMA block for current chunk (covers the LDG latency) ----
        #pragma unroll
        for (int ks = 0; ks < 2; ks++) {
            uint32_t Ah[2][4], Al[2][4];
            #pragma unroll
            for (int mt = 0; mt < 2; mt++) {
                uint32_t off;
                if (!TA) {
                    uint32_t row = (uint32_t)(am + mt * 16 + (lane & 15));
                    uint32_t cb  = (uint32_t)(ks * 32 + ((lane >> 4) << 4));
                    off = off_rk(row, cb);
                } else {
                    uint32_t grp = lane >> 3, t8 = lane & 7;
                    uint32_t k   = (uint32_t)(ks * 16) + ((grp >> 1) << 3) + t8;
                    uint32_t cb  = (uint32_t)(am + mt * 16 + ((grp & 1) << 3)) * 2;
                    off = off_kn(k, cb);
                }
                if (!TA) {
                    ldsm4(Ah[mt][0], Ah[mt][1], Ah[mt][2], Ah[mt][3], uAh + off);
                    ldsm4(Al[mt][0], Al[mt][1], Al[mt][2], Al[mt][3], uAl + off);
                } else {
                    ldsm4t(Ah[mt][0], Ah[mt][1], Ah[mt][2], Ah[mt][3], uAh + off);
                    ldsm4t(Al[mt][0], Al[mt][1], Al[mt][2], Al[mt][3], uAl + off);
                }
            }
            uint32_t Bh[8][2], Bl[8][2];
            #pragma unroll
            for (int p = 0; p < 4; p++) {
                uint32_t off;
                if (!TB) {
                    uint32_t row = (uint32_t)(bn + p * 16 + (lane & 15));
                    uint32_t cb  = (uint32_t)(ks * 32 + ((lane >> 4) << 4));
                    off = off_rk(row, cb);
                } else {
                    uint32_t grp = lane >> 3, t8 = lane & 7;
                    uint32_t k   = (uint32_t)(ks * 16) + ((grp >> 1) << 3) + t8;
                    uint32_t cb  = (uint32_t)(bn + p * 16 + ((grp & 1) << 3)) * 2;
                    off = off_kn(k, cb);
                }
                uint32_t r0, r1, r2, r3;
                if (!TB) ldsm4 (r0, r1, r2, r3, uBh + off);
                else     ldsm4t(r0, r1, r2, r3, uBh + off);
                Bh[2*p][0] = r0; Bh[2*p][1] = r2; Bh[2*p+1][0] = r1; Bh[2*p+1][1] = r3;
                if (!TB) ldsm4 (r0, r1, r2, r3, uBl + off);
                else     ldsm4t(r0, r1, r2, r3, uBl + off);
                Bl[2*p][0] = r0; Bl[2*p][1] = r2; Bl[2*p+1][0] = r1; Bl[2*p+1][1] = r3;
            }
            // 3-product MMAs, R3's original interleaved order
            #pragma unroll
            for (int mt = 0; mt < 2; mt++)
                #pragma unroll
                for (int nt = 0; nt < 8; nt++) {
                    mma16816(acc[mt][nt], Ah[mt], Bh[nt]);
                    mma16816(acc[mt][nt], Ah[mt], Bl[nt]);
                    mma16816(acc[mt][nt], Al[mt], Bh[nt]);
                }
        }

        // ---- 3) commit next chunk: cvt + STS into the other stage ----
        if (more) {
            char* nxt = smem + (d ^ 1) * STG;
            stage_store<TA>(pa, nxt,         nxt + 8192,  tid);
            stage_store<TB>(pb, nxt + 16384, nxt + 24576, tid);
        }
        __syncthreads();
    }

    // ---- epilogue ----
    #pragma unroll
    for (int mt = 0; mt < 2; mt++) {
        #pragma unroll
        for (int half = 0; half < 2; half++) {
            int row = m0 + am + mt * 16 + (lane >> 2) + half * 8;
            float* crow = Cb + (long)row * ldc + n0 + bn + (lane & 3) * 2;
            const float* arow = (EPI == 3)
                ? Add + (long)b * sAdd + (long)row * ldc + n0 + bn + (lane & 3) * 2 : nullptr;
            #pragma unroll
            for (int nt = 0; nt < 8; nt++) {
                float x = acc[mt][nt][half * 2 + 0];
                float y = acc[mt][nt][half * 2 + 1];
                if (EPI >= 1) { x = fmaxf(x, 0.f); y = fmaxf(y, 0.f); }
                if (EPI == 2) { float2 o = *(const float2*)&crow[nt * 8]; x += o.x; y += o.y; }
                if (EPI == 3) { float2 o = *(const float2*)&arow[nt * 8]; x += o.x; y += o.y; }
                float2 v; v.x = x; v.y = y;
                *(float2*)&crow[nt * 8] = v;
            }
        }
    }
}

// ---------------------------------------------------------------------------
// Row softmax over last dim (256), in place.
// ---------------------------------------------------------------------------
__global__ __launch_bounds__(256)
void softmax_kernel(float* __restrict__ S)
{
    __shared__ float sm[8];
    const long row = blockIdx.x;
    float* p = S + row * (long)NN;
    const int t = threadIdx.x;

    float v = p[t];
    float m = v;
    #pragma unroll
    for (int o = 16; o > 0; o >>= 1) m = fmaxf(m, __shfl_xor_sync(0xffffffffu, m, o));
    if ((t & 31) == 0) sm[t >> 5] = m;
    __syncthreads();
    m = sm[0];
    #pragma unroll
    for (int i = 1; i < 8; i++) m = fmaxf(m, sm[i]);

    float e = expf(v - m);
    float s = e;
    #pragma unroll
    for (int o = 16; o > 0; o >>= 1) s += __shfl_xor_sync(0xffffffffu, s, o);
    __syncthreads();
    if ((t & 31) == 0) sm[t >> 5] = s;
    __syncthreads();
    s = 0.f;
    #pragma unroll
    for (int i = 0; i < 8; i++) s += sm[i];

    p[t] = e / s;
}

// ---------------------------------------------------------------------------
extern "C" void kernel_launch(void* const* d_in, const int* in_sizes, int n_in,
                              void* d_out, int out_size)
{
    const float* f     = (const float*)d_in[0];
    const float* adj   = (const float*)d_in[2];
    const float* Wse1  = (const float*)d_in[3];
    const float* Wse2  = (const float*)d_in[4];
    const float* Wst1  = (const float*)d_in[5];
    const float* Wst2  = (const float*)d_in[6];
    const float* Wst3  = (const float*)d_in[7];
    const float* Wst1b = (const float*)d_in[8];
    const float* Wst2b = (const float*)d_in[9];
    const float* Wst3b = (const float*)d_in[10];
    const float* Wsim1 = (const float*)d_in[11];
    const float* Wsim2 = (const float*)d_in[12];
    const float* Wsim3 = (const float*)d_in[13];
    float* out = (float*)d_out;

    float *b1, *b2, *b3, *b4, *S;
    cudaGetSymbolAddress((void**)&b1, g_b1);
    cudaGetSymbolAddress((void**)&b2, g_b2);
    cudaGetSymbolAddress((void**)&b3, g_b3);
    cudaGetSymbolAddress((void**)&b4, g_b4);
    cudaGetSymbolAddress((void**)&S,  g_S);

    cudaFuncSetAttribute(tc_gemm<0,0,0>, cudaFuncAttributeMaxDynamicSharedMemorySize, SMEM_TOTAL);
    cudaFuncSetAttribute(tc_gemm<0,1,0>, cudaFuncAttributeMaxDynamicSharedMemorySize, SMEM_TOTAL);
    cudaFuncSetAttribute(tc_gemm<0,1,1>, cudaFuncAttributeMaxDynamicSharedMemorySize, SMEM_TOTAL);
    cudaFuncSetAttribute(tc_gemm<1,1,2>, cudaFuncAttributeMaxDynamicSharedMemorySize, SMEM_TOTAL);
    cudaFuncSetAttribute(tc_gemm<0,1,3>, cudaFuncAttributeMaxDynamicSharedMemorySize, SMEM_TOTAL);

    const dim3 blk(256);
    const dim3 g1(CC/128, NN/128, BSZ);   // (4,2,64): M=256, N=512
    const dim3 g3(NN/128, NN/128, BSZ);   // (2,2,64): M=256, N=256
    const int SM = SMEM_TOTAL;

    // similarity graph: S = softmax((f Wse1^T)(f Wse2^T)^T)
    tc_gemm<0,0,0><<<g1, blk, SM>>>(f, NC, CC, Wse1, 0, CC, b1, NC, CC, nullptr, 0, CC);
    tc_gemm<0,0,0><<<g1, blk, SM>>>(f, NC, CC, Wse2, 0, CC, b2, NC, CC, nullptr, 0, CC);
    tc_gemm<0,0,0><<<g3, blk, SM>>>(b1, NC, CC, b2, NC, CC, S, NNN, NN, nullptr, 0, CC);
    softmax_kernel<<<BSZ*NN, blk>>>(S);

    // st branch layer 1 -> b1
    tc_gemm<0,1,0><<<g1, blk, SM>>>(f, NC, CC, Wst1,  0, CC, b3, NC, CC, nullptr, 0, CC);
    tc_gemm<0,1,0><<<g1, blk, SM>>>(f, NC, CC, Wst1b, 0, CC, b4, NC, CC, nullptr, 0, CC);
    tc_gemm<0,1,1><<<g1, blk, SM>>>(adj, NNN, NN, b3, NC, CC, b1, NC, CC, nullptr, 0, NN);
    tc_gemm<1,1,2><<<g1, blk, SM>>>(adj, NNN, NN, b4, NC, CC, b1, NC, CC, nullptr, 0, NN);
    // layer 2 -> b2
    tc_gemm<0,1,0><<<g1, blk, SM>>>(b1, NC, CC, Wst2,  0, CC, b3, NC, CC, nullptr, 0, CC);
    tc_gemm<0,1,0><<<g1, blk, SM>>>(b1, NC, CC, Wst2b, 0, CC, b4, NC, CC, nullptr, 0, CC);
    tc_gemm<0,1,1><<<g1, blk, SM>>>(adj, NNN, NN, b3, NC, CC, b2, NC, CC, nullptr, 0, NN);
    tc_gemm<1,1,2><<<g1, blk, SM>>>(adj, NNN, NN, b4, NC, CC, b2, NC, CC, nullptr, 0, NN);
    // layer 3 -> b1
    tc_gemm<0,1,0><<<g1, blk, SM>>>(b2, NC, CC, Wst3,  0, CC, b3, NC, CC, nullptr, 0, CC);
    tc_gemm<0,1,0><<<g1, blk, SM>>>(b2, NC, CC, Wst3b, 0, CC, b4, NC, CC, nullptr, 0, CC);
    tc_gemm<0,1,1><<<g1, blk, SM>>>(adj, NNN, NN, b3, NC, CC, b1, NC, CC, nullptr, 0, NN);
    tc_gemm<1,1,2><<<g1, blk, SM>>>(adj, NNN, NN, b4, NC, CC, b1, NC, CC, nullptr, 0, NN);

    // sim branch
    tc_gemm<0,1,0><<<g1, blk, SM>>>(f, NC, CC, Wsim1, 0, CC, b3, NC, CC, nullptr, 0, CC);
    tc_gemm<0,1,1><<<g1, blk, SM>>>(S, NNN, NN, b3, NC, CC, b2, NC, CC, nullptr, 0, NN);
    tc_gemm<0,1,0><<<g1, blk, SM>>>(b2, NC, CC, Wsim2, 0, CC, b3, NC, CC, nullptr, 0, CC);
    tc_gemm<0,1,1><<<g1, blk, SM>>>(S, NNN, NN, b3, NC, CC, b4, NC, CC, nullptr, 0, NN);
    tc_gemm<0,1,0><<<g1, blk, SM>>>(b4, NC, CC, Wsim3, 0, CC, b3, NC, CC, nullptr, 0, CC);
    // out = relu(S @ Y3) + st
    tc_gemm<0,1,3><<<g1, blk, SM>>>(S, NNN, NN, b3, NC, CC, out, NC, CC, b1, NC, NN);
}

// round 9
// speedup vs baseline: 1.2541x; 1.2541x over previous
#include <cuda_runtime.h>
#include <cuda_bf16.h>
#include <math.h>
#include <stdint.h>

#define BSZ 64
#define NN  256
#define CC  512
#define NC  (NN*CC)     // 131072
#define NNN (NN*NN)     // 65536

// Scratch (no cudaMalloc allowed)
__device__ float g_b1[BSZ*NC];
__device__ float g_b2[BSZ*NC];
__device__ float g_b3[BSZ*NC];
__device__ float g_b4[BSZ*NC];
__device__ float g_b5[BSZ*NC];
__device__ float g_b6[BSZ*NC];
__device__ float g_c5[BSZ*NC];
__device__ float g_S [BSZ*NNN];

// SMEM stage layout: Ah @0 (8KB) | Al @8K | Bh @16K | Bl @24K ; two stages.
#define STG        32768
#define SMEM_TOTAL (2*STG)

__device__ __forceinline__ uint32_t smem_u32(const void* p) {
    uint32_t a;
    asm("{ .reg .u64 t; cvta.to.shared.u64 t, %1; cvt.u32.u64 %0, t; }" : "=r"(a) : "l"(p));
    return a;
}

// [row][k] layout, 128 rows x 64B; swizzle keeps ldmatrix phases conflict-free
__device__ __forceinline__ uint32_t off_rk(uint32_t r, uint32_t cb) {
    return r * 64u + ((((cb >> 4) ^ ((r >> 1) & 3u)) & 3u) << 4) + (cb & 15u);
}
// [k][col] layout, 32 rows x 256B
__device__ __forceinline__ uint32_t off_kn(uint32_t k, uint32_t cb) {
    uint32_t ch = (cb >> 4) ^ (k & 7u);
    return k * 256u + (ch << 4) + (cb & 15u);
}

__device__ __forceinline__ void ldsm4(uint32_t& r0, uint32_t& r1, uint32_t& r2, uint32_t& r3, uint32_t a) {
    asm volatile("ldmatrix.sync.aligned.m8n8.x4.shared.b16 {%0,%1,%2,%3}, [%4];"
                 : "=r"(r0), "=r"(r1), "=r"(r2), "=r"(r3) : "r"(a));
}
__device__ __forceinline__ void ldsm4t(uint32_t& r0, uint32_t& r1, uint32_t& r2, uint32_t& r3, uint32_t a) {
    asm volatile("ldmatrix.sync.aligned.m8n8.x4.trans.shared.b16 {%0,%1,%2,%3}, [%4];"
                 : "=r"(r0), "=r"(r1), "=r"(r2), "=r"(r3) : "r"(a));
}
__device__ __forceinline__ void mma16816(float* c, const uint32_t* a, const uint32_t* b) {
    asm volatile(
        "mma.sync.aligned.m16n8k16.row.col.f32.bf16.bf16.f32 "
        "{%0,%1,%2,%3}, {%4,%5,%6,%7}, {%8,%9}, {%0,%1,%2,%3};"
        : "+f"(c[0]), "+f"(c[1]), "+f"(c[2]), "+f"(c[3])
        : "r"(a[0]), "r"(a[1]), "r"(a[2]), "r"(a[3]), "r"(b[0]), "r"(b[1]));
}

// Convert 8 fp32 -> 8 bf16 hi + 8 bf16 lo, write 16B each.
__device__ __forceinline__ void cvt_store8(const float4 v0, const float4 v1,
                                           char* ph, char* pl) {
    float v[8] = {v0.x, v0.y, v0.z, v0.w, v1.x, v1.y, v1.z, v1.w};
    unsigned short hs[8], ls[8];
    #pragma unroll
    for (int e = 0; e < 8; e++) {
        __nv_bfloat16 hb = __float2bfloat16_rn(v[e]);
        float lf = v[e] - __bfloat162float(hb);
        __nv_bfloat16 lb = __float2bfloat16_rn(lf);
        hs[e] = *(unsigned short*)&hb;
        ls[e] = *(unsigned short*)&lb;
    }
    *(uint4*)ph = *(uint4*)hs;
    *(uint4*)pl = *(uint4*)ls;
}

// Stage one 128x32 operand tile (fp32 -> bf16 hi/lo split).
// T=0: source row-major rows=tile rows (m or n), ld over k.  layout [r][k].
// T=1: source row-major rows=k (transposed operand).          layout [k][c].
// src2 (optional, uniform): element-wise fp32 add before splitting.
template<int T>
__device__ __forceinline__ void stage_tile(const float* __restrict__ src,
                                           const float* __restrict__ src2, int ld,
                                           int k0, int r0,
                                           char* sh, char* sl, int tid) {
    if (T == 0) {
        #pragma unroll
        for (int it = 0; it < 2; it++) {
            int idx = it * 256 + tid;
            int r = idx >> 2, cb8 = (idx & 3) * 8;
            long o = (long)(r0 + r) * ld + k0 + cb8;
            float4 a = *(const float4*)(src + o);
            float4 b = *(const float4*)(src + o + 4);
            if (src2) {
                float4 a2 = *(const float4*)(src2 + o);
                float4 b2 = *(const float4*)(src2 + o + 4);
                a.x += a2.x; a.y += a2.y; a.z += a2.z; a.w += a2.w;
                b.x += b2.x; b.y += b2.y; b.z += b2.z; b.w += b2.w;
            }
            uint32_t off = off_rk((uint32_t)r, (uint32_t)cb8 * 2);
            cvt_store8(a, b, sh + off, sl + off);
        }
    } else {
        #pragma unroll
        for (int it = 0; it < 2; it++) {
            int idx = it * 256 + tid;
            int kr = idx >> 4, cb8 = (idx & 15) * 8;
            long o = (long)(k0 + kr) * ld + r0 + cb8;
            float4 a = *(const float4*)(src + o);
            float4 b = *(const float4*)(src + o + 4);
            if (src2) {
                float4 a2 = *(const float4*)(src2 + o);
                float4 b2 = *(const float4*)(src2 + o + 4);
                a.x += a2.x; a.y += a2.y; a.z += a2.z; a.w += a2.w;
                b.x += b2.x; b.y += b2.y; b.z += b2.z; b.w += b2.w;
            }
            uint32_t off = off_kn((uint32_t)kr, (uint32_t)cb8 * 2);
            cvt_store8(a, b, sh + off, sl + off);
        }
    }
}

// ---------------------------------------------------------------------------
// GEMM body (exactly R3's mainloop).  C[b](128 x 128 tile of M x N)
//   TA=0: A row-major (M,K).  TA=1: A[m][k] = src[k*lda+m] (adj^T).
//   TB=0: B source (N,K) row-major.  TB=1: B[n][k] = src[k*ldb+n].
//   EPI: 0 store | 1 relu | 3 relu + Add1 + Add2
// ---------------------------------------------------------------------------
template<int TA, int TB, int EPI>
__device__ __forceinline__ void gemm_body(
    const float* __restrict__ A, const float* __restrict__ Asum,
    const float* __restrict__ B, float* __restrict__ C,
    const float* __restrict__ Add1, const float* __restrict__ Add2,
    long sA, int lda, long sB, int ldb, long sC, int ldc, int K,
    char* smem, int nx)
{
    const int tid = threadIdx.x, lane = tid & 31, wid = tid >> 5;
    const int b  = blockIdx.z;
    const int m0 = blockIdx.y * 128;
    const int n0 = nx * 128;
    const float* Ab  = A + (long)b * sA;
    const float* Asb = Asum ? (Asum + (long)b * sA) : nullptr;
    const float* Bb  = B + (long)b * sB;
    float*       Cb  = C + (long)b * sC;

    const int am = (wid & 3) * 32;   // warp rows
    const int bn = (wid >> 2) * 64;  // warp cols

    float acc[2][8][4];
    #pragma unroll
    for (int i = 0; i < 2; i++)
        #pragma unroll
        for (int j = 0; j < 8; j++)
            #pragma unroll
            for (int e = 0; e < 4; e++) acc[i][j][e] = 0.f;

    const int nch = K >> 5;

    stage_tile<TA>(Ab, Asb, lda, 0, m0, smem,          smem + 8192,  tid);
    stage_tile<TB>(Bb, nullptr, ldb, 0, n0, smem + 16384, smem + 24576, tid);
    __syncthreads();

    for (int ch = 0; ch < nch; ch++) {
        const int d = ch & 1;
        char* cur = smem + d * STG;
        if (ch + 1 < nch) {
            char* nxt = smem + (d ^ 1) * STG;
            stage_tile<TA>(Ab, Asb, lda, (ch + 1) << 5, m0, nxt,         nxt + 8192,  tid);
            stage_tile<TB>(Bb, nullptr, ldb, (ch + 1) << 5, n0, nxt + 16384, nxt + 24576, tid);
        }
        const uint32_t uAh = smem_u32(cur);
        const uint32_t uAl = uAh + 8192;
        const uint32_t uBh = uAh + 16384;
        const uint32_t uBl = uAh + 24576;

        #pragma unroll
        for (int ks = 0; ks < 2; ks++) {
            uint32_t Ah[2][4], Al[2][4];
            #pragma unroll
            for (int mt = 0; mt < 2; mt++) {
                uint32_t off;
                if (!TA) {
                    uint32_t row = (uint32_t)(am + mt * 16 + (lane & 15));
                    uint32_t cb  = (uint32_t)(ks * 32 + ((lane >> 4) << 4));
                    off = off_rk(row, cb);
                } else {
                    uint32_t grp = lane >> 3, t8 = lane & 7;
                    uint32_t k   = (uint32_t)(ks * 16) + ((grp >> 1) << 3) + t8;
                    uint32_t cb  = (uint32_t)(am + mt * 16 + ((grp & 1) << 3)) * 2;
                    off = off_kn(k, cb);
                }
                if (!TA) {
                    ldsm4(Ah[mt][0], Ah[mt][1], Ah[mt][2], Ah[mt][3], uAh + off);
                    ldsm4(Al[mt][0], Al[mt][1], Al[mt][2], Al[mt][3], uAl + off);
                } else {
                    ldsm4t(Ah[mt][0], Ah[mt][1], Ah[mt][2], Ah[mt][3], uAh + off);
                    ldsm4t(Al[mt][0], Al[mt][1], Al[mt][2], Al[mt][3], uAl + off);
                }
            }
            uint32_t Bh[8][2], Bl[8][2];
            #pragma unroll
            for (int p = 0; p < 4; p++) {
                uint32_t off;
                if (!TB) {
                    uint32_t row = (uint32_t)(bn + p * 16 + (lane & 15));
                    uint32_t cb  = (uint32_t)(ks * 32 + ((lane >> 4) << 4));
                    off = off_rk(row, cb);
                } else {
                    uint32_t grp = lane >> 3, t8 = lane & 7;
                    uint32_t k   = (uint32_t)(ks * 16) + ((grp >> 1) << 3) + t8;
                    uint32_t cb  = (uint32_t)(bn + p * 16 + ((grp & 1) << 3)) * 2;
                    off = off_kn(k, cb);
                }
                uint32_t r0, r1, r2, r3;
                if (!TB) ldsm4 (r0, r1, r2, r3, uBh + off);
                else     ldsm4t(r0, r1, r2, r3, uBh + off);
                Bh[2*p][0] = r0; Bh[2*p][1] = r2; Bh[2*p+1][0] = r1; Bh[2*p+1][1] = r3;
                if (!TB) ldsm4 (r0, r1, r2, r3, uBl + off);
                else     ldsm4t(r0, r1, r2, r3, uBl + off);
                Bl[2*p][0] = r0; Bl[2*p][1] = r2; Bl[2*p+1][0] = r1; Bl[2*p+1][1] = r3;
            }
            // 3-product MMAs, R3's original interleaved order
            #pragma unroll
            for (int mt = 0; mt < 2; mt++)
                #pragma unroll
                for (int nt = 0; nt < 8; nt++) {
                    mma16816(acc[mt][nt], Ah[mt], Bh[nt]);
                    mma16816(acc[mt][nt], Ah[mt], Bl[nt]);
                    mma16816(acc[mt][nt], Al[mt], Bh[nt]);
                }
        }
        __syncthreads();
    }

    // ---- epilogue ----
    #pragma unroll
    for (int mt = 0; mt < 2; mt++) {
        #pragma unroll
        for (int half = 0; half < 2; half++) {
            int row = m0 + am + mt * 16 + (lane >> 2) + half * 8;
            float* crow = Cb + (long)row * ldc + n0 + bn + (lane & 3) * 2;
            long abase = (long)b * sC + (long)row * ldc + n0 + bn + (lane & 3) * 2;
            #pragma unroll
            for (int nt = 0; nt < 8; nt++) {
                float x = acc[mt][nt][half * 2 + 0];
                float y = acc[mt][nt][half * 2 + 1];
                if (EPI >= 1) { x = fmaxf(x, 0.f); y = fmaxf(y, 0.f); }
                if (EPI == 3) {
                    float2 o1 = *(const float2*)(Add1 + abase + nt * 8);
                    float2 o2 = *(const float2*)(Add2 + abase + nt * 8);
                    x += (o1.x + o2.x); y += (o1.y + o2.y);
                }
                float2 v; v.x = x; v.y = y;
                *(float2*)&crow[nt * 8] = v;
            }
        }
    }
}

// ---------------------------------------------------------------------------
// Multi-part GEMM launcher kernel: part = blockIdx.x >> 2 (all parts N=512;
// for PARTS=1 / N=256 the shift is harmless). Per-part compile-time TA.
// ---------------------------------------------------------------------------
template<int TB, int EPI, int PARTS, int TA0, int TA1, int TA2>
__global__ __launch_bounds__(256)
void tc_gemm_multi(
    const float* A0, const float* A1, const float* A2,
    const float* As0, const float* As1, const float* As2,
    const float* B0, const float* B1, const float* B2,
    float* C0, float* C1, float* C2,
    const float* Add1, const float* Add2,
    long sA, int lda, long sB, int ldb, long sC, int ldc, int K)
{
    extern __shared__ char smem[];
    const int p  = blockIdx.x >> 2;
    const int nx = blockIdx.x & 3;
    if (PARTS >= 3 && p == 2) {
        gemm_body<TA2, TB, EPI>(A2, As2, B2, C2, Add1, Add2,
                                sA, lda, sB, ldb, sC, ldc, K, smem, nx);
    } else if (PARTS >= 2 && p == 1) {
        gemm_body<TA1, TB, EPI>(A1, As1, B1, C1, Add1, Add2,
                                sA, lda, sB, ldb, sC, ldc, K, smem, nx);
    } else {
        gemm_body<TA0, TB, EPI>(A0, As0, B0, C0, Add1, Add2,
                                sA, lda, sB, ldb, sC, ldc, K, smem, nx);
    }
}

// ---------------------------------------------------------------------------
// Row softmax over last dim (256), in place.
// ---------------------------------------------------------------------------
__global__ __launch_bounds__(256)
void softmax_kernel(float* __restrict__ S)
{
    __shared__ float sm[8];
    const long row = blockIdx.x;
    float* p = S + row * (long)NN;
    const int t = threadIdx.x;

    float v = p[t];
    float m = v;
    #pragma unroll
    for (int o = 16; o > 0; o >>= 1) m = fmaxf(m, __shfl_xor_sync(0xffffffffu, m, o));
    if ((t & 31) == 0) sm[t >> 5] = m;
    __syncthreads();
    m = sm[0];
    #pragma unroll
    for (int i = 1; i < 8; i++) m = fmaxf(m, sm[i]);

    float e = expf(v - m);
    float s = e;
    #pragma unroll
    for (int o = 16; o > 0; o >>= 1) s += __shfl_xor_sync(0xffffffffu, s, o);
    __syncthreads();
    if ((t & 31) == 0) sm[t >> 5] = s;
    __syncthreads();
    s = 0.f;
    #pragma unroll
    for (int i = 0; i < 8; i++) s += sm[i];

    p[t] = e / s;
}

// Kernel type aliases (template instantiations)
#define K_SEP  tc_gemm_multi<0,0,2, 0,0,0>   // b1=f@Wse1^T, b2=f@Wse2^T
#define K_SGM  tc_gemm_multi<0,0,1, 0,0,0>   // S = b1 @ b2^T
#define K_W3   tc_gemm_multi<1,0,3, 0,0,0>   // three X@W muls (opt ASUM)
#define K_G3   tc_gemm_multi<1,1,3, 0,0,1>   // S@c, adj@b3, adjT@b4 (relu)
#define K_G2   tc_gemm_multi<1,1,2, 0,1,0>   // adj@b3, adjT@b4 (relu)
#define K_FIN  tc_gemm_multi<1,3,1, 0,0,0>   // out = relu(S@c5)+b5+b6

// ---------------------------------------------------------------------------
extern "C" void kernel_launch(void* const* d_in, const int* in_sizes, int n_in,
                              void* d_out, int out_size)
{
    const float* f     = (const float*)d_in[0];
    const float* adj   = (const float*)d_in[2];
    const float* Wse1  = (const float*)d_in[3];
    const float* Wse2  = (const float*)d_in[4];
    const float* Wst1  = (const float*)d_in[5];
    const float* Wst2  = (const float*)d_in[6];
    const float* Wst3  = (const float*)d_in[7];
    const float* Wst1b = (const float*)d_in[8];
    const float* Wst2b = (const float*)d_in[9];
    const float* Wst3b = (const float*)d_in[10];
    const float* Wsim1 = (const float*)d_in[11];
    const float* Wsim2 = (const float*)d_in[12];
    const float* Wsim3 = (const float*)d_in[13];
    float* out = (float*)d_out;

    float *b1, *b2, *b3, *b4, *b5, *b6, *c5, *S;
    cudaGetSymbolAddress((void**)&b1, g_b1);
    cudaGetSymbolAddress((void**)&b2, g_b2);
    cudaGetSymbolAddress((void**)&b3, g_b3);
    cudaGetSymbolAddress((void**)&b4, g_b4);
    cudaGetSymbolAddress((void**)&b5, g_b5);
    cudaGetSymbolAddress((void**)&b6, g_b6);
    cudaGetSymbolAddress((void**)&c5, g_c5);
    cudaGetSymbolAddress((void**)&S,  g_S);

    cudaFuncSetAttribute(K_SEP, cudaFuncAttributeMaxDynamicSharedMemorySize, SMEM_TOTAL);
    cudaFuncSetAttribute(K_SGM, cudaFuncAttributeMaxDynamicSharedMemorySize, SMEM_TOTAL);
    cudaFuncSetAttribute(K_W3,  cudaFuncAttributeMaxDynamicSharedMemorySize, SMEM_TOTAL);
    cudaFuncSetAttribute(K_G3,  cudaFuncAttributeMaxDynamicSharedMemorySize, SMEM_TOTAL);
    cudaFuncSetAttribute(K_G2,  cudaFuncAttributeMaxDynamicSharedMemorySize, SMEM_TOTAL);
    cudaFuncSetAttribute(K_FIN, cudaFuncAttributeMaxDynamicSharedMemorySize, SMEM_TOTAL);

    const dim3 blk(256);
    const dim3 gp2(8, 2, BSZ);    // 2 parts, N=512
    const dim3 gp3(12, 2, BSZ);   // 3 parts, N=512
    const dim3 gs(2, 2, BSZ);     // solo, N=256
    const dim3 g1(4, 2, BSZ);     // solo, N=512
    const int SM = SMEM_TOTAL;
    const float* Z = nullptr;
    float* ZC = nullptr;

    // 1) b1 = f@Wse1^T, b2 = f@Wse2^T  (TB=0, paired)
    K_SEP<<<gp2, blk, SM>>>(f, f, Z, Z, Z, Z, Wse1, Wse2, Z, b1, b2, ZC, Z, Z,
                            NC, CC, 0, CC, NC, CC, CC);
    // 2) S = b1 @ b2^T
    K_SGM<<<gs, blk, SM>>>(b1, Z, Z, Z, Z, Z, b2, Z, Z, S, ZC, ZC, Z, Z,
                           NC, CC, NC, CC, NNN, NN, CC);
    // 3) softmax rows of S
    softmax_kernel<<<BSZ*NN, blk>>>(S);

    // 4) stage A: b3=f@Wst1, b4=f@Wst1b, b1<-c1=f@Wsim1
    K_W3<<<gp3, blk, SM>>>(f, f, f, Z, Z, Z, Wst1, Wst1b, Wsim1, b3, b4, b1, Z, Z,
                           NC, CC, 0, CC, NC, CC, CC);
    // 5) stage B: b5=relu(adj@b3), b6=relu(adjT@b4), b2<-c2=relu(S@b1)
    K_G3<<<gp3, blk, SM>>>(adj, S, adj, Z, Z, Z, b3, b1, b4, b5, b2, b6, Z, Z,
                           NNN, NN, NC, CC, NC, CC, NN);
    // 6) stage C: b3=(b5+b6)@Wst2, b4=(b5+b6)@Wst2b, b1<-c3=b2@Wsim2
    K_W3<<<gp3, blk, SM>>>(b5, b5, b2, b6, b6, Z, Wst2, Wst2b, Wsim2, b3, b4, b1, Z, Z,
                           NC, CC, 0, CC, NC, CC, CC);
    // 7) stage D: b5=relu(adj@b3), b6=relu(adjT@b4), b2<-c4=relu(S@b1)
    K_G3<<<gp3, blk, SM>>>(adj, S, adj, Z, Z, Z, b3, b1, b4, b5, b2, b6, Z, Z,
                           NNN, NN, NC, CC, NC, CC, NN);
    // 8) stage E: b3=(b5+b6)@Wst3, b4=(b5+b6)@Wst3b, c5=b2@Wsim3
    K_W3<<<gp3, blk, SM>>>(b5, b5, b2, b6, b6, Z, Wst3, Wst3b, Wsim3, b3, b4, c5, Z, Z,
                           NC, CC, 0, CC, NC, CC, CC);
    // 9) stage F: b5=relu(adj@b3), b6=relu(adjT@b4)
    K_G2<<<gp2, blk, SM>>>(adj, adj, Z, Z, Z, Z, b3, b4, Z, b5, b6, ZC, Z, Z,
                           NNN, NN, NC, CC, NC, CC, NN);
    // 10) out = relu(S@c5) + b5 + b6
    K_FIN<<<g1, blk, SM>>>(S, Z, Z, Z, Z, Z, c5, Z, Z, out, ZC, ZC, b5, b6,
                           NNN, NN, NC, CC, NC, CC, NN);
}

// round 10
// speedup vs baseline: 1.3285x; 1.0593x over previous
#include <cuda_runtime.h>
#include <cuda_bf16.h>
#include <math.h>
#include <stdint.h>

typedef __nv_bfloat16 bf16;

#define BSZ 64
#define NN  256
#define CC  512
#define NC  (NN*CC)     // 131072
#define NNN (NN*NN)     // 65536
#define WSZ (CC*CC)     // 262144

// fp32 scratch
__device__ float g_b1[BSZ*NC];
__device__ float g_b2[BSZ*NC];
__device__ float g_b3[BSZ*NC];
__device__ float g_b4[BSZ*NC];
__device__ float g_b5[BSZ*NC];
__device__ float g_b6[BSZ*NC];
__device__ float g_c5[BSZ*NC];
__device__ float g_S [BSZ*NNN];
__device__ float g_M [WSZ];
// bf16 hi/lo leaf operands
__device__ __align__(256) bf16 g_fh[BSZ*NC],  g_fl[BSZ*NC];
__device__ __align__(256) bf16 g_ajh[BSZ*NNN], g_ajl[BSZ*NNN];
__device__ __align__(256) bf16 g_wh[9*WSZ],   g_wl[9*WSZ];
__device__ __align__(256) bf16 g_mh[WSZ],     g_ml[WSZ];

#define STG        32768
#define SMEM_TOTAL (2*STG)

__device__ __forceinline__ uint32_t smem_u32(const void* p) {
    uint32_t a;
    asm("{ .reg .u64 t; cvta.to.shared.u64 t, %1; cvt.u32.u64 %0, t; }" : "=r"(a) : "l"(p));
    return a;
}
__device__ __forceinline__ uint32_t off_rk(uint32_t r, uint32_t cb) {
    return r * 64u + ((((cb >> 4) ^ ((r >> 1) & 3u)) & 3u) << 4) + (cb & 15u);
}
__device__ __forceinline__ uint32_t off_kn(uint32_t k, uint32_t cb) {
    uint32_t ch = (cb >> 4) ^ (k & 7u);
    return k * 256u + (ch << 4) + (cb & 15u);
}
__device__ __forceinline__ void ldsm4(uint32_t& r0, uint32_t& r1, uint32_t& r2, uint32_t& r3, uint32_t a) {
    asm volatile("ldmatrix.sync.aligned.m8n8.x4.shared.b16 {%0,%1,%2,%3}, [%4];"
                 : "=r"(r0), "=r"(r1), "=r"(r2), "=r"(r3) : "r"(a));
}
__device__ __forceinline__ void ldsm4t(uint32_t& r0, uint32_t& r1, uint32_t& r2, uint32_t& r3, uint32_t a) {
    asm volatile("ldmatrix.sync.aligned.m8n8.x4.trans.shared.b16 {%0,%1,%2,%3}, [%4];"
                 : "=r"(r0), "=r"(r1), "=r"(r2), "=r"(r3) : "r"(a));
}
__device__ __forceinline__ void mma16816(float* c, const uint32_t* a, const uint32_t* b) {
    asm volatile(
        "mma.sync.aligned.m16n8k16.row.col.f32.bf16.bf16.f32 "
        "{%0,%1,%2,%3}, {%4,%5,%6,%7}, {%8,%9}, {%0,%1,%2,%3};"
        : "+f"(c[0]), "+f"(c[1]), "+f"(c[2]), "+f"(c[3])
        : "r"(a[0]), "r"(a[1]), "r"(a[2]), "r"(a[3]), "r"(b[0]), "r"(b[1]));
}
__device__ __forceinline__ void cvt_store8(const float4 v0, const float4 v1,
                                           char* ph, char* pl) {
    float v[8] = {v0.x, v0.y, v0.z, v0.w, v1.x, v1.y, v1.z, v1.w};
    unsigned short hs[8], ls[8];
    #pragma unroll
    for (int e = 0; e < 8; e++) {
        __nv_bfloat16 hb = __float2bfloat16_rn(v[e]);
        float lf = v[e] - __bfloat162float(hb);
        __nv_bfloat16 lb = __float2bfloat16_rn(lf);
        hs[e] = *(unsigned short*)&hb;
        ls[e] = *(unsigned short*)&lb;
    }
    *(uint4*)ph = *(uint4*)hs;
    *(uint4*)pl = *(uint4*)ls;
}

// Stage one 128x32 tile into hi/lo smem.
// T=0: rows = tile rows; layout [r][k]. T=1: rows = k; layout [k][c].
// P=0: fp32 source (+optional fp32 src2 add). P=1: prepacked bf16 hi/lo source.
template<int T, int P>
__device__ __forceinline__ void stage_tile(const float* __restrict__ srcf,
                                           const float* __restrict__ src2,
                                           const bf16* __restrict__ s16h,
                                           const bf16* __restrict__ s16l,
                                           int ld, int k0, int r0,
                                           char* sh, char* sl, int tid) {
    #pragma unroll
    for (int it = 0; it < 2; it++) {
        int idx = it * 256 + tid;
        int r, cb8;
        if (T == 0) { r = idx >> 2; cb8 = (idx & 3) * 8; }
        else        { r = idx >> 4; cb8 = (idx & 15) * 8; }
        long o = (T == 0) ? ((long)(r0 + r) * ld + k0 + cb8)
                          : ((long)(k0 + r) * ld + r0 + cb8);
        uint32_t off = (T == 0) ? off_rk((uint32_t)r, (uint32_t)cb8 * 2)
                                : off_kn((uint32_t)r, (uint32_t)cb8 * 2);
        if (P) {
            *(uint4*)(sh + off) = *(const uint4*)(s16h + o);
            *(uint4*)(sl + off) = *(const uint4*)(s16l + o);
        } else {
            float4 a = *(const float4*)(srcf + o);
            float4 b = *(const float4*)(srcf + o + 4);
            if (src2) {
                float4 a2 = *(const float4*)(src2 + o);
                float4 b2 = *(const float4*)(src2 + o + 4);
                a.x += a2.x; a.y += a2.y; a.z += a2.z; a.w += a2.w;
                b.x += b2.x; b.y += b2.y; b.z += b2.z; b.w += b2.w;
            }
            cvt_store8(a, b, sh + off, sl + off);
        }
    }
}

// ---------------------------------------------------------------------------
// GEMM body (R3/R9 proven mainloop, untouched).
//   PA/PB: operand prepacked (bf16 pair) vs fp32 (A2 = optional add).
//   EPI: 0 store | 1 relu | 3 relu + Add1 + Add2
// ---------------------------------------------------------------------------
template<int TA, int TB, int PA, int PB, int EPI>
__device__ __forceinline__ void gemm_body(
    const void* __restrict__ A, const void* __restrict__ A2,
    const void* __restrict__ B, const void* __restrict__ B2,
    float* __restrict__ C,
    const float* __restrict__ Add1, const float* __restrict__ Add2,
    long sA, int lda, long sB, int ldb, long sC, int ldc, int K,
    char* smem, int nx)
{
    const int tid = threadIdx.x, lane = tid & 31, wid = tid >> 5;
    const int b  = blockIdx.z;
    const int m0 = blockIdx.y * 128;
    const int n0 = nx * 128;

    const float* Af  = PA ? nullptr : ((const float*)A + (long)b * sA);
    const float* Af2 = (!PA && A2) ? ((const float*)A2 + (long)b * sA) : nullptr;
    const bf16*  Ah16 = PA ? ((const bf16*)A  + (long)b * sA) : nullptr;
    const bf16*  Al16 = PA ? ((const bf16*)A2 + (long)b * sA) : nullptr;
    const float* Bf  = PB ? nullptr : ((const float*)B + (long)b * sB);
    const bf16*  Bh16 = PB ? ((const bf16*)B  + (long)b * sB) : nullptr;
    const bf16*  Bl16 = PB ? ((const bf16*)B2 + (long)b * sB) : nullptr;
    float* Cb = C + (long)b * sC;

    const int am = (wid & 3) * 32;
    const int bn = (wid >> 2) * 64;

    float acc[2][8][4];
    #pragma unroll
    for (int i = 0; i < 2; i++)
        #pragma unroll
        for (int j = 0; j < 8; j++)
            #pragma unroll
            for (int e = 0; e < 4; e++) acc[i][j][e] = 0.f;

    const int nch = K >> 5;

    stage_tile<TA,PA>(Af, Af2, Ah16, Al16, lda, 0, m0, smem,         smem + 8192,  tid);
    stage_tile<TB,PB>(Bf, nullptr, Bh16, Bl16, ldb, 0, n0, smem + 16384, smem + 24576, tid);
    __syncthreads();

    for (int ch = 0; ch < nch; ch++) {
        const int d = ch & 1;
        char* cur = smem + d * STG;
        if (ch + 1 < nch) {
            char* nxt = smem + (d ^ 1) * STG;
            stage_tile<TA,PA>(Af, Af2, Ah16, Al16, lda, (ch + 1) << 5, m0, nxt,         nxt + 8192,  tid);
            stage_tile<TB,PB>(Bf, nullptr, Bh16, Bl16, ldb, (ch + 1) << 5, n0, nxt + 16384, nxt + 24576, tid);
        }
        const uint32_t uAh = smem_u32(cur);
        const uint32_t uAl = uAh + 8192;
        const uint32_t uBh = uAh + 16384;
        const uint32_t uBl = uAh + 24576;

        #pragma unroll
        for (int ks = 0; ks < 2; ks++) {
            uint32_t Ahf[2][4], Alf[2][4];
            #pragma unroll
            for (int mt = 0; mt < 2; mt++) {
                uint32_t off;
                if (!TA) {
                    uint32_t row = (uint32_t)(am + mt * 16 + (lane & 15));
                    uint32_t cb  = (uint32_t)(ks * 32 + ((lane >> 4) << 4));
                    off = off_rk(row, cb);
                } else {
                    uint32_t grp = lane >> 3, t8 = lane & 7;
                    uint32_t k   = (uint32_t)(ks * 16) + ((grp >> 1) << 3) + t8;
                    uint32_t cb  = (uint32_t)(am + mt * 16 + ((grp & 1) << 3)) * 2;
                    off = off_kn(k, cb);
                }
                if (!TA) {
                    ldsm4(Ahf[mt][0], Ahf[mt][1], Ahf[mt][2], Ahf[mt][3], uAh + off);
                    ldsm4(Alf[mt][0], Alf[mt][1], Alf[mt][2], Alf[mt][3], uAl + off);
                } else {
                    ldsm4t(Ahf[mt][0], Ahf[mt][1], Ahf[mt][2], Ahf[mt][3], uAh + off);
                    ldsm4t(Alf[mt][0], Alf[mt][1], Alf[mt][2], Alf[mt][3], uAl + off);
                }
            }
            uint32_t Bhf[8][2], Blf[8][2];
            #pragma unroll
            for (int p = 0; p < 4; p++) {
                uint32_t off;
                if (!TB) {
                    uint32_t row = (uint32_t)(bn + p * 16 + (lane & 15));
                    uint32_t cb  = (uint32_t)(ks * 32 + ((lane >> 4) << 4));
                    off = off_rk(row, cb);
                } else {
                    uint32_t grp = lane >> 3, t8 = lane & 7;
                    uint32_t k   = (uint32_t)(ks * 16) + ((grp >> 1) << 3) + t8;
                    uint32_t cb  = (uint32_t)(bn + p * 16 + ((grp & 1) << 3)) * 2;
                    off = off_kn(k, cb);
                }
                uint32_t r0, r1, r2, r3;
                if (!TB) ldsm4 (r0, r1, r2, r3, uBh + off);
                else     ldsm4t(r0, r1, r2, r3, uBh + off);
                Bhf[2*p][0] = r0; Bhf[2*p][1] = r2; Bhf[2*p+1][0] = r1; Bhf[2*p+1][1] = r3;
                if (!TB) ldsm4 (r0, r1, r2, r3, uBl + off);
                else     ldsm4t(r0, r1, r2, r3, uBl + off);
                Blf[2*p][0] = r0; Blf[2*p][1] = r2; Blf[2*p+1][0] = r1; Blf[2*p+1][1] = r3;
            }
            #pragma unroll
            for (int mt = 0; mt < 2; mt++)
                #pragma unroll
                for (int nt = 0; nt < 8; nt++) {
                    mma16816(acc[mt][nt], Ahf[mt], Bhf[nt]);
                    mma16816(acc[mt][nt], Ahf[mt], Blf[nt]);
                    mma16816(acc[mt][nt], Alf[mt], Bhf[nt]);
                }
        }
        __syncthreads();
    }

    #pragma unroll
    for (int mt = 0; mt < 2; mt++) {
        #pragma unroll
        for (int half = 0; half < 2; half++) {
            int row = m0 + am + mt * 16 + (lane >> 2) + half * 8;
            float* crow = Cb + (long)row * ldc + n0 + bn + (lane & 3) * 2;
            long abase = (long)b * sC + (long)row * ldc + n0 + bn + (lane & 3) * 2;
            #pragma unroll
            for (int nt = 0; nt < 8; nt++) {
                float x = acc[mt][nt][half * 2 + 0];
                float y = acc[mt][nt][half * 2 + 1];
                if (EPI >= 1) { x = fmaxf(x, 0.f); y = fmaxf(y, 0.f); }
                if (EPI == 3) {
                    float2 o1 = *(const float2*)(Add1 + abase + nt * 8);
                    float2 o2 = *(const float2*)(Add2 + abase + nt * 8);
                    x += (o1.x + o2.x); y += (o1.y + o2.y);
                }
                float2 v; v.x = x; v.y = y;
                *(float2*)&crow[nt * 8] = v;
            }
        }
    }
}

// ---------------------------------------------------------------------------
// Multi-part launcher: part = blockIdx.x >> 2, nx = blockIdx.x & 3.
// ---------------------------------------------------------------------------
template<int PARTS,
         int TA0,int TB0,int PA0,int PB0,int EPI0,
         int TA1,int TB1,int PA1,int PB1,int EPI1,
         int TA2,int TB2,int PA2,int PB2,int EPI2,
         int TA3,int TB3,int PA3,int PB3,int EPI3>
__global__ __launch_bounds__(256)
void tc_multi(
    const void* A0, const void* A20, const void* B0, const void* B20, float* C0,
    const void* A1, const void* A21, const void* B1, const void* B21, float* C1,
    const void* A2, const void* A22, const void* B2, const void* B22, float* C2,
    const void* A3, const void* A23, const void* B3, const void* B23, float* C3,
    const float* Add1, const float* Add2,
    long sA, int lda, long sB, int ldb, long sC, int ldc, int K)
{
    extern __shared__ char smem[];
    const int p  = blockIdx.x >> 2;
    const int nx = blockIdx.x & 3;
    if (PARTS >= 4 && p == 3)
        gemm_body<TA3,TB3,PA3,PB3,EPI3>(A3, A23, B3, B23, C3, Add1, Add2,
                                        sA, lda, sB, ldb, sC, ldc, K, smem, nx);
    else if (PARTS >= 3 && p == 2)
        gemm_body<TA2,TB2,PA2,PB2,EPI2>(A2, A22, B2, B22, C2, Add1, Add2,
                                        sA, lda, sB, ldb, sC, ldc, K, smem, nx);
    else if (PARTS >= 2 && p == 1)
        gemm_body<TA1,TB1,PA1,PB1,EPI1>(A1, A21, B1, B21, C1, Add1, Add2,
                                        sA, lda, sB, ldb, sC, ldc, K, smem, nx);
    else
        gemm_body<TA0,TB0,PA0,PB0,EPI0>(A0, A20, B0, B20, C0, Add1, Add2,
                                        sA, lda, sB, ldb, sC, ldc, K, smem, nx);
}

// ---------------------------------------------------------------------------
__global__ __launch_bounds__(256)
void softmax_kernel(float* __restrict__ S)
{
    __shared__ float sm[8];
    const long row = blockIdx.x;
    float* p = S + row * (long)NN;
    const int t = threadIdx.x;

    float v = p[t];
    float m = v;
    #pragma unroll
    for (int o = 16; o > 0; o >>= 1) m = fmaxf(m, __shfl_xor_sync(0xffffffffu, m, o));
    if ((t & 31) == 0) sm[t >> 5] = m;
    __syncthreads();
    m = sm[0];
    #pragma unroll
    for (int i = 1; i < 8; i++) m = fmaxf(m, sm[i]);

    float e = expf(v - m);
    float s = e;
    #pragma unroll
    for (int o = 16; o > 0; o >>= 1) s += __shfl_xor_sync(0xffffffffu, s, o);
    __syncthreads();
    if ((t & 31) == 0) sm[t >> 5] = s;
    __syncthreads();
    s = 0.f;
    #pragma unroll
    for (int i = 0; i < 8; i++) s += sm[i];

    p[t] = e / s;
}

// ---------------------------------------------------------------------------
// Pack fp32 -> bf16 hi/lo (8 elems/thread)
// ---------------------------------------------------------------------------
__global__ __launch_bounds__(256)
void pack8(const float* __restrict__ src, bf16* __restrict__ dh, bf16* __restrict__ dl, long n8)
{
    long i = (long)blockIdx.x * 256 + threadIdx.x;
    if (i >= n8) return;
    long o = i * 8;
    float4 a = *(const float4*)(src + o);
    float4 b = *(const float4*)(src + o + 4);
    cvt_store8(a, b, (char*)(dh + o), (char*)(dl + o));
}

__global__ __launch_bounds__(256)
void pack_w9(const float* s0, const float* s1, const float* s2, const float* s3,
             const float* s4, const float* s5, const float* s6, const float* s7,
             const float* s8, bf16* __restrict__ dh, bf16* __restrict__ dl)
{
    long i = (long)blockIdx.x * 256 + threadIdx.x;
    long o = i * 8;
    int which = (int)(o >> 18);
    long off = o & (WSZ - 1);
    const float* s;
    switch (which) {
        case 0: s = s0; break; case 1: s = s1; break; case 2: s = s2; break;
        case 3: s = s3; break; case 4: s = s4; break; case 5: s = s5; break;
        case 6: s = s6; break; case 7: s = s7; break; default: s = s8; break;
    }
    float4 a = *(const float4*)(s + off);
    float4 b = *(const float4*)(s + off + 4);
    cvt_store8(a, b, (char*)(dh + o), (char*)(dl + o));
}

// Instantiation macros
#define KM  tc_multi<1, 1,1,0,0,0, 0,0,0,0,0, 0,0,0,0,0, 0,0,0,0,0>
#define KW4 tc_multi<4, 0,1,1,1,0, 0,1,1,1,0, 0,1,1,1,0, 0,1,1,1,0>
#define KSG tc_multi<1, 0,0,0,1,0, 0,0,0,0,0, 0,0,0,0,0, 0,0,0,0,0>
#define KG3 tc_multi<3, 0,1,1,0,1, 0,1,0,0,1, 1,1,1,0,1, 0,0,0,0,0>
#define KW3 tc_multi<3, 0,1,0,1,0, 0,1,0,1,0, 0,1,0,1,0, 0,0,0,0,0>
#define KG2 tc_multi<2, 0,1,1,0,1, 1,1,1,0,1, 0,0,0,0,0, 0,0,0,0,0>
#define KFI tc_multi<1, 0,1,0,0,3, 0,0,0,0,0, 0,0,0,0,0, 0,0,0,0,0>

// ---------------------------------------------------------------------------
extern "C" void kernel_launch(void* const* d_in, const int* in_sizes, int n_in,
                              void* d_out, int out_size)
{
    const float* f     = (const float*)d_in[0];
    const float* adj   = (const float*)d_in[2];
    const float* Wse1  = (const float*)d_in[3];
    const float* Wse2  = (const float*)d_in[4];
    const float* Wst1  = (const float*)d_in[5];
    const float* Wst2  = (const float*)d_in[6];
    const float* Wst3  = (const float*)d_in[7];
    const float* Wst1b = (const float*)d_in[8];
    const float* Wst2b = (const float*)d_in[9];
    const float* Wst3b = (const float*)d_in[10];
    const float* Wsim1 = (const float*)d_in[11];
    const float* Wsim2 = (const float*)d_in[12];
    const float* Wsim3 = (const float*)d_in[13];
    float* out = (float*)d_out;

    float *b1, *b2, *b3, *b4, *b5, *b6, *c5, *S, *M;
    bf16 *fh, *fl, *ajh, *ajl, *wh, *wl, *mh, *ml;
    cudaGetSymbolAddress((void**)&b1, g_b1);  cudaGetSymbolAddress((void**)&b2, g_b2);
    cudaGetSymbolAddress((void**)&b3, g_b3);  cudaGetSymbolAddress((void**)&b4, g_b4);
    cudaGetSymbolAddress((void**)&b5, g_b5);  cudaGetSymbolAddress((void**)&b6, g_b6);
    cudaGetSymbolAddress((void**)&c5, g_c5);  cudaGetSymbolAddress((void**)&S,  g_S);
    cudaGetSymbolAddress((void**)&M,  g_M);
    cudaGetSymbolAddress((void**)&fh,  g_fh);  cudaGetSymbolAddress((void**)&fl,  g_fl);
    cudaGetSymbolAddress((void**)&ajh, g_ajh); cudaGetSymbolAddress((void**)&ajl, g_ajl);
    cudaGetSymbolAddress((void**)&wh,  g_wh);  cudaGetSymbolAddress((void**)&wl,  g_wl);
    cudaGetSymbolAddress((void**)&mh,  g_mh);  cudaGetSymbolAddress((void**)&ml,  g_ml);

    cudaFuncSetAttribute(KM,  cudaFuncAttributeMaxDynamicSharedMemorySize, SMEM_TOTAL);
    cudaFuncSetAttribute(KW4, cudaFuncAttributeMaxDynamicSharedMemorySize, SMEM_TOTAL);
    cudaFuncSetAttribute(KSG, cudaFuncAttributeMaxDynamicSharedMemorySize, SMEM_TOTAL);
    cudaFuncSetAttribute(KG3, cudaFuncAttributeMaxDynamicSharedMemorySize, SMEM_TOTAL);
    cudaFuncSetAttribute(KW3, cudaFuncAttributeMaxDynamicSharedMemorySize, SMEM_TOTAL);
    cudaFuncSetAttribute(KG2, cudaFuncAttributeMaxDynamicSharedMemorySize, SMEM_TOTAL);
    cudaFuncSetAttribute(KFI, cudaFuncAttributeMaxDynamicSharedMemorySize, SMEM_TOTAL);

    const dim3 blk(256);
    const int SM = SMEM_TOTAL;
    const void* Z = nullptr;
    float* ZC = nullptr;

    // weight pack order: 0=Wst1 1=Wst1b 2=Wst2 3=Wst2b 4=Wst3 5=Wst3b 6=Wsim1 7=Wsim2 8=Wsim3
    #define WH(i) ((const void*)(wh + (long)(i)*WSZ))
    #define WL(i) ((const void*)(wl + (long)(i)*WSZ))

    // ---- packs ----
    pack_w9<<<9*WSZ/8/256, blk>>>(Wst1, Wst1b, Wst2, Wst2b, Wst3, Wst3b,
                                  Wsim1, Wsim2, Wsim3, wh, wl);
    pack8<<<(int)((long)BSZ*NC/8/256),  blk>>>(f,   fh,  fl,  (long)BSZ*NC/8);
    pack8<<<(int)((long)BSZ*NNN/8/256), blk>>>(adj, ajh, ajl, (long)BSZ*NNN/8);

    // ---- M = Wse1^T @ Wse2 (512x512x512, 1 batch) ----
    KM<<<dim3(4,4,1), blk, SM>>>(Wse1, Z, Wse2, Z, M,
                                 Z, Z, Z, Z, ZC,  Z, Z, Z, Z, ZC,  Z, Z, Z, Z, ZC,
                                 nullptr, nullptr, 0, CC, 0, CC, 0, CC, CC);
    pack8<<<WSZ/8/256, blk>>>(M, mh, ml, WSZ/8);

    // ---- stage A: b3=f@Wst1, b4=f@Wst1b, b1=f@Wsim1, b2=f@M (all prepacked) ----
    KW4<<<dim3(16,2,BSZ), blk, SM>>>(
        fh, fl, WH(0), WL(0), b3,
        fh, fl, WH(1), WL(1), b4,
        fh, fl, WH(6), WL(6), b1,
        fh, fl, mh,    ml,    b2,
        nullptr, nullptr, NC, CC, 0, CC, NC, CC, CC);

    // ---- S = b2 @ f^T, then softmax ----
    KSG<<<dim3(2,2,BSZ), blk, SM>>>(
        b2, Z, fh, fl, S,
        Z, Z, Z, Z, ZC,  Z, Z, Z, Z, ZC,  Z, Z, Z, Z, ZC,
        nullptr, nullptr, NC, CC, NC, CC, NNN, NN, CC);
    softmax_kernel<<<BSZ*NN, blk>>>(S);

    // ---- stage B: b5=relu(adj@b3), b2=relu(S@b1), b6=relu(adjT@b4) ----
    KG3<<<dim3(12,2,BSZ), blk, SM>>>(
        ajh, ajl, b3, Z, b5,
        S,   Z,   b1, Z, b2,
        ajh, ajl, b4, Z, b6,
        Z, Z, Z, Z, ZC,
        nullptr, nullptr, NNN, NN, NC, CC, NC, CC, NN);

    // ---- stage C: b3=(b5+b6)@Wst2, b4=(b5+b6)@Wst2b, b1=b2@Wsim2 ----
    KW3<<<dim3(12,2,BSZ), blk, SM>>>(
        b5, b6, WH(2), WL(2), b3,
        b5, b6, WH(3), WL(3), b4,
        b2, Z,  WH(7), WL(7), b1,
        Z, Z, Z, Z, ZC,
        nullptr, nullptr, NC, CC, 0, CC, NC, CC, CC);

    // ---- stage D ----
    KG3<<<dim3(12,2,BSZ), blk, SM>>>(
        ajh, ajl, b3, Z, b5,
        S,   Z,   b1, Z, b2,
        ajh, ajl, b4, Z, b6,
        Z, Z, Z, Z, ZC,
        nullptr, nullptr, NNN, NN, NC, CC, NC, CC, NN);

    // ---- stage E: b3=(b5+b6)@Wst3, b4=(b5+b6)@Wst3b, c5=b2@Wsim3 ----
    KW3<<<dim3(12,2,BSZ), blk, SM>>>(
        b5, b6, WH(4), WL(4), b3,
        b5, b6, WH(5), WL(5), b4,
        b2, Z,  WH(8), WL(8), c5,
        Z, Z, Z, Z, ZC,
        nullptr, nullptr, NC, CC, 0, CC, NC, CC, CC);

    // ---- stage F: b5=relu(adj@b3), b6=relu(adjT@b4) ----
    KG2<<<dim3(8,2,BSZ), blk, SM>>>(
        ajh, ajl, b3, Z, b5,
        ajh, ajl, b4, Z, b6,
        Z, Z, Z, Z, ZC,  Z, Z, Z, Z, ZC,
        nullptr, nullptr, NNN, NN, NC, CC, NC, CC, NN);

    // ---- out = relu(S@c5) + b5 + b6 ----
    KFI<<<dim3(4,2,BSZ), blk, SM>>>(
        S, Z, c5, Z, out,
        Z, Z, Z, Z, ZC,  Z, Z, Z, Z, ZC,  Z, Z, Z, Z, ZC,
        b5, b6, NNN, NN, NC, CC, NC, CC, NN);
}